// round 1
// baseline (speedup 1.0000x reference)
#include <cuda_runtime.h>
#include <cuda_bf16.h>
#include <math.h>

// ---------------- problem constants ----------------
#define LAYERS 2
#define D      1024
#define H      16
#define DH     64
#define FF     4096
#define NE     8
#define TOPK   2
#define V      32000
#define IH     4
#define ID     64
#define IHD    256   // IH*ID
#define B      2
#define S      1024
#define NT     2048  // B*S
#define KSEL   512
#define NEGV   (-1e9f)
#define EPS    1e-5f

// ---------------- scratch ----------------
// offsets in floats; M2 = 2M floats (one [NT,D] buffer)
#define M2 2097152UL
// h, hn, q, k, v, att, qi+ki, iscore, y(8*M2), hidden(32*M2)
__device__ float g_buf[48UL * M2];

#define OFF_H   (0UL)
#define OFF_HN  (1UL * M2)
#define OFF_Q   (2UL * M2)
#define OFF_K   (3UL * M2)
#define OFF_V   (4UL * M2)
#define OFF_ATT (5UL * M2)
#define OFF_QI  (6UL * M2)            // NT*IHD = 524288
#define OFF_KI  (6UL * M2 + 524288UL)
#define OFF_IS  (7UL * M2)            // NT*S = M2
#define OFF_Y   (8UL * M2)            // NE*2048*D = 8*M2
#define OFF_HID (16UL * M2)           // NE*2048*FF = 32*M2

__device__ unsigned g_selmask[NT * 32];
__device__ int      g_elist[NE * NT];
__device__ int      g_ecount[NE];
__device__ int      g_tope[NT * 2];
__device__ float    g_gate[NT * 2];
__device__ int      g_slot[NT * 2];

// ---------------- helpers ----------------
__device__ __forceinline__ float gelu_f(float x) {
    // jax.nn.gelu approximate=True (tanh)
    const float c = 0.7978845608028654f;
    float x3 = x * x * x;
    return 0.5f * x * (1.0f + tanhf(c * (x + 0.044715f * x3)));
}

// ---------------- embedding ----------------
__global__ void embed_kernel(const int* __restrict__ ids,
                             const float* __restrict__ tok_emb,
                             const float* __restrict__ pos_emb,
                             float* __restrict__ h) {
    long idx = (long)blockIdx.x * blockDim.x + threadIdx.x;
    if (idx >= (long)NT * D) return;
    int tok = (int)(idx / D);
    int d   = (int)(idx % D);
    int s   = tok % S;
    h[idx] = tok_emb[(long)ids[tok] * D + d] + pos_emb[(long)s * D + d];
}

// ---------------- layernorm (per row of D) ----------------
__global__ void ln_kernel(const float* __restrict__ x,
                          const float* __restrict__ g,
                          const float* __restrict__ b,
                          float* __restrict__ y) {
    int row = blockIdx.x;
    int t = threadIdx.x;
    __shared__ float red[256];
    __shared__ float s_mean, s_inv;
    const float* xr = x + (long)row * D;
    float s = 0.f;
    for (int i = t; i < D; i += 256) s += xr[i];
    red[t] = s; __syncthreads();
    for (int o = 128; o > 0; o >>= 1) { if (t < o) red[t] += red[t + o]; __syncthreads(); }
    if (t == 0) s_mean = red[0] / (float)D;
    __syncthreads();
    float m = s_mean;
    float s2 = 0.f;
    for (int i = t; i < D; i += 256) { float d = xr[i] - m; s2 += d * d; }
    red[t] = s2; __syncthreads();
    for (int o = 128; o > 0; o >>= 1) { if (t < o) red[t] += red[t + o]; __syncthreads(); }
    if (t == 0) s_inv = rsqrtf(red[0] / (float)D + EPS);
    __syncthreads();
    float inv = s_inv;
    float* yr = y + (long)row * D;
    for (int i = t; i < D; i += 256) yr[i] = (xr[i] - m) * inv * g[i] + b[i];
}

// ---------------- generic SGEMM: C[N,M] = act(A[N,K] @ W[K,M] + bias) (+ resid) ----------------
// 64x64 tile, BK=16, 256 threads, 4x4 per thread. Optional row gather (row_idx),
// optional dynamic row count (*n_ptr), act: 0=none, 1=gelu.
__global__ __launch_bounds__(256)
void sgemm_kernel(const float* __restrict__ A, const float* __restrict__ W,
                  const float* __restrict__ bias, const float* __restrict__ resid,
                  float* __restrict__ C, int N, int M, int K,
                  const int* __restrict__ row_idx, const int* __restrict__ n_ptr,
                  int act) {
    int n = n_ptr ? *n_ptr : N;
    int br = blockIdx.y * 64;
    int bc = blockIdx.x * 64;
    if (br >= n) return;

    __shared__ float As[16][64];
    __shared__ float Bs[16][64];

    int t = threadIdx.x;
    int tx = t & 15, ty = t >> 4;

    int ar = t >> 2;            // 0..63 (tile row for A load)
    int ac4 = (t & 3) * 4;      // k within tile (float4)
    int gr = br + ar;
    long arow = 0;
    if (gr < n) arow = row_idx ? (long)row_idx[gr] : (long)gr;

    int bk = t >> 4;            // 0..15 (k row for B load)
    int bc4 = (t & 15) * 4;     // col within tile (float4)

    float acc[4][4];
#pragma unroll
    for (int i = 0; i < 4; i++)
#pragma unroll
        for (int j = 0; j < 4; j++) acc[i][j] = 0.f;

    for (int k0 = 0; k0 < K; k0 += 16) {
        float4 av = *(const float4*)&A[arow * (long)K + k0 + ac4];
        As[ac4 + 0][ar] = av.x;
        As[ac4 + 1][ar] = av.y;
        As[ac4 + 2][ar] = av.z;
        As[ac4 + 3][ar] = av.w;
        float4 bv = *(const float4*)&W[(long)(k0 + bk) * M + bc + bc4];
        *(float4*)&Bs[bk][bc4] = bv;
        __syncthreads();
#pragma unroll
        for (int kk = 0; kk < 16; kk++) {
            float a0 = As[kk][ty * 4 + 0];
            float a1 = As[kk][ty * 4 + 1];
            float a2 = As[kk][ty * 4 + 2];
            float a3 = As[kk][ty * 4 + 3];
            float4 bvv = *(const float4*)&Bs[kk][tx * 4];
            acc[0][0] += a0 * bvv.x; acc[0][1] += a0 * bvv.y; acc[0][2] += a0 * bvv.z; acc[0][3] += a0 * bvv.w;
            acc[1][0] += a1 * bvv.x; acc[1][1] += a1 * bvv.y; acc[1][2] += a1 * bvv.z; acc[1][3] += a1 * bvv.w;
            acc[2][0] += a2 * bvv.x; acc[2][1] += a2 * bvv.y; acc[2][2] += a2 * bvv.z; acc[2][3] += a2 * bvv.w;
            acc[3][0] += a3 * bvv.x; acc[3][1] += a3 * bvv.y; acc[3][2] += a3 * bvv.z; acc[3][3] += a3 * bvv.w;
        }
        __syncthreads();
    }

#pragma unroll
    for (int i = 0; i < 4; i++) {
        int row = br + ty * 4 + i;
        if (row >= n) continue;
#pragma unroll
        for (int j = 0; j < 4; j++) {
            int col = bc + tx * 4 + j;
            float v = acc[i][j];
            if (bias) v += bias[col];
            if (act == 1) v = gelu_f(v);
            if (resid) v += resid[(long)row * M + col];
            C[(long)row * M + col] = v;
        }
    }
}

// ---------------- indexer scores ----------------
__global__ void idx_score_kernel(const float* __restrict__ qi,
                                 const float* __restrict__ ki,
                                 const float* __restrict__ hw,
                                 float* __restrict__ sc) {
    int row = blockIdx.x;     // b*S + q
    int b = row / S;
    int t = threadIdx.x;      // 256
    __shared__ float qs[IHD];
    __shared__ float w[IH];
    if (t < IHD) qs[t] = qi[(long)row * IHD + t];
    if (t < IH) w[t] = hw[t];
    __syncthreads();
    for (int k = t; k < S; k += 256) {
        const float* kr = ki + (long)(b * S + k) * IHD;
        float s = 0.f;
#pragma unroll
        for (int hh = 0; hh < IH; hh++) {
            float d = 0.f;
#pragma unroll
            for (int i = 0; i < ID; i++) d += qs[hh * ID + i] * kr[hh * ID + i];
            s += w[hh] * fmaxf(d, 0.f);
        }
        sc[(long)row * S + k] = s;
    }
}

// ---------------- exact stable top-k selection (rank counting) ----------------
__global__ void topk_kernel(const float* __restrict__ sc, unsigned* __restrict__ sel) {
    int row = blockIdx.x;
    int t = threadIdx.x;  // 1024
    __shared__ float s[S];
    s[t] = sc[(long)row * S + t];
    __syncthreads();
    float v = s[t];
    int cnt = 0;
    for (int i = 0; i < S; i++) {
        float si = s[i];
        cnt += (si > v) || (si == v && i < t);
    }
    unsigned ball = __ballot_sync(0xffffffffu, cnt < KSEL);
    if ((t & 31) == 0) sel[row * 32 + (t >> 5)] = ball;
}

// ---------------- fused attention (per b,h,q row) ----------------
__global__ void attn_kernel(const float* __restrict__ q, const float* __restrict__ k,
                            const float* __restrict__ v, const unsigned* __restrict__ selmask,
                            float* __restrict__ out) {
    int idx = blockIdx.x;          // b*H*S + h*S + q
    int qpos = idx % S;
    int hh = (idx / S) % H;
    int b = idx / (S * H);
    int t = threadIdx.x;           // 256

    __shared__ float qs[DH];
    __shared__ float sc[S];
    __shared__ float red[256];
    __shared__ float s_max, s_inv;

    const float* qrow = q + ((long)(b * S + qpos) * D + hh * DH);
    if (t < DH) qs[t] = qrow[t];
    __syncthreads();

    const unsigned* selrow = selmask + (long)(b * S + qpos) * 32;
    for (int kk = t; kk < S; kk += 256) {
        const float* krow = k + ((long)(b * S + kk) * D + hh * DH);
        float d = 0.f;
#pragma unroll
        for (int i = 0; i < DH; i++) d += qs[i] * krow[i];
        d *= 0.125f;  // 1/sqrt(64)
        bool allowed = (kk <= qpos) && ((selrow[kk >> 5] >> (kk & 31)) & 1u);
        sc[kk] = allowed ? d : (d + NEGV);
    }
    __syncthreads();

    // max
    float m = -INFINITY;
    for (int kk = t; kk < S; kk += 256) m = fmaxf(m, sc[kk]);
    red[t] = m; __syncthreads();
    for (int o = 128; o > 0; o >>= 1) { if (t < o) red[t] = fmaxf(red[t], red[t + o]); __syncthreads(); }
    if (t == 0) s_max = red[0];
    __syncthreads();
    float mx = s_max;

    // exp + sum
    float sum = 0.f;
    for (int kk = t; kk < S; kk += 256) {
        float p = expf(sc[kk] - mx);
        sc[kk] = p;
        sum += p;
    }
    red[t] = sum; __syncthreads();
    for (int o = 128; o > 0; o >>= 1) { if (t < o) red[t] += red[t + o]; __syncthreads(); }
    if (t == 0) s_inv = 1.f / red[0];
    __syncthreads();
    float inv = s_inv;

    // AV: 64 dims x 4 key-chunks
    int d = t & 63;
    int chunk = t >> 6;  // 0..3
    float acc = 0.f;
    int kbeg = chunk * 256, kend = kbeg + 256;
    for (int kk = kbeg; kk < kend; kk++)
        acc += sc[kk] * v[(long)(b * S + kk) * D + hh * DH + d];
    red[t] = acc; __syncthreads();
    if (t < 64) {
        float o = (red[t] + red[t + 64] + red[t + 128] + red[t + 192]) * inv;
        out[(long)(b * S + qpos) * D + hh * DH + t] = o;
    }
}

// ---------------- router (per token): softmax over 8, stable top-2, list build ----------------
__global__ void router_kernel(const float* __restrict__ x, const float* __restrict__ w,
                              const float* __restrict__ bias,
                              int* __restrict__ tope, float* __restrict__ gate,
                              int* __restrict__ slot, int* __restrict__ elist,
                              int* __restrict__ ecount) {
    int tkn = blockIdx.x;
    int t = threadIdx.x;  // 256
    int e = t >> 5, lane = t & 31;
    __shared__ float logit[NE];
    const float* xr = x + (long)tkn * D;
    float s = 0.f;
    for (int i = lane; i < D; i += 32) s += xr[i] * w[(long)i * NE + e];
#pragma unroll
    for (int o = 16; o > 0; o >>= 1) s += __shfl_down_sync(0xffffffffu, s, o);
    if (lane == 0) logit[e] = s + bias[e];
    __syncthreads();
    if (t == 0) {
        float mx = logit[0];
        for (int i = 1; i < NE; i++) mx = fmaxf(mx, logit[i]);
        float p[NE]; float sum = 0.f;
        for (int i = 0; i < NE; i++) { p[i] = expf(logit[i] - mx); sum += p[i]; }
        float invs = 1.f / sum;
        for (int i = 0; i < NE; i++) p[i] *= invs;
        int i0 = 0;
        for (int i = 1; i < NE; i++) if (p[i] > p[i0]) i0 = i;
        int i1 = -1;
        for (int i = 0; i < NE; i++) { if (i == i0) continue; if (i1 < 0 || p[i] > p[i1]) i1 = i; }
        float g0 = p[i0], g1 = p[i1];
        float ginv = 1.f / (g0 + g1);
        g0 *= ginv; g1 *= ginv;
        tope[2 * tkn] = i0; tope[2 * tkn + 1] = i1;
        gate[2 * tkn] = g0; gate[2 * tkn + 1] = g1;
        int s0 = atomicAdd(&ecount[i0], 1); elist[i0 * NT + s0] = tkn; slot[2 * tkn] = s0;
        int s1 = atomicAdd(&ecount[i1], 1); elist[i1 * NT + s1] = tkn; slot[2 * tkn + 1] = s1;
    }
}

__global__ void zero_counts_kernel(int* __restrict__ ecount) {
    if (threadIdx.x < NE) ecount[threadIdx.x] = 0;
}

// ---------------- MoE gather: h += g0*y[e0][slot0] + g1*y[e1][slot1] ----------------
__global__ void moe_gather_kernel(const float* __restrict__ y, const int* __restrict__ tope,
                                  const float* __restrict__ gate, const int* __restrict__ slot,
                                  float* __restrict__ h) {
    long idx = (long)blockIdx.x * blockDim.x + threadIdx.x;
    if (idx >= (long)NT * D) return;
    int tkn = (int)(idx / D);
    int d = (int)(idx % D);
    int e0 = tope[2 * tkn], e1 = tope[2 * tkn + 1];
    float g0 = gate[2 * tkn], g1 = gate[2 * tkn + 1];
    long r0 = (long)(e0 * NT + slot[2 * tkn]) * D + d;
    long r1 = (long)(e1 * NT + slot[2 * tkn + 1]) * D + d;
    h[idx] += g0 * y[r0] + g1 * y[r1];
}

// ---------------- launch ----------------
extern "C" void kernel_launch(void* const* d_in, const int* in_sizes, int n_in,
                              void* d_out, int out_size) {
    const int*   input_ids = (const int*)d_in[0];
    const float* tok_emb   = (const float*)d_in[1];
    const float* pos_emb   = (const float*)d_in[2];
    const float* ind_qw    = (const float*)d_in[3];
    const float* ind_qb    = (const float*)d_in[4];
    const float* ind_kw    = (const float*)d_in[5];
    const float* ind_kb    = (const float*)d_in[6];
    const float* ind_hw    = (const float*)d_in[7];
    const float* an_g      = (const float*)d_in[8];
    const float* an_b      = (const float*)d_in[9];
    const float* q_w       = (const float*)d_in[10];
    const float* q_b       = (const float*)d_in[11];
    const float* k_w       = (const float*)d_in[12];
    const float* k_b       = (const float*)d_in[13];
    const float* v_w       = (const float*)d_in[14];
    const float* v_b       = (const float*)d_in[15];
    const float* o_w       = (const float*)d_in[16];
    const float* o_b       = (const float*)d_in[17];
    const float* mn_g      = (const float*)d_in[18];
    const float* mn_b      = (const float*)d_in[19];
    const float* router_w  = (const float*)d_in[20];
    const float* router_b  = (const float*)d_in[21];
    const float* e_w1      = (const float*)d_in[22];
    const float* e_b1      = (const float*)d_in[23];
    const float* e_w2      = (const float*)d_in[24];
    const float* e_b2      = (const float*)d_in[25];
    const float* ln_g      = (const float*)d_in[26];
    const float* ln_b      = (const float*)d_in[27];
    const float* out_w     = (const float*)d_in[28];
    const float* out_b     = (const float*)d_in[29];
    float* out = (float*)d_out;

    float* buf = nullptr;
    cudaGetSymbolAddress((void**)&buf, g_buf);
    unsigned* selmask = nullptr; cudaGetSymbolAddress((void**)&selmask, g_selmask);
    int* elist = nullptr;  cudaGetSymbolAddress((void**)&elist, g_elist);
    int* ecount = nullptr; cudaGetSymbolAddress((void**)&ecount, g_ecount);
    int* tope = nullptr;   cudaGetSymbolAddress((void**)&tope, g_tope);
    float* gate = nullptr; cudaGetSymbolAddress((void**)&gate, g_gate);
    int* slot = nullptr;   cudaGetSymbolAddress((void**)&slot, g_slot);

    float* h    = buf + OFF_H;
    float* hn   = buf + OFF_HN;
    float* qb   = buf + OFF_Q;
    float* kb   = buf + OFF_K;
    float* vb   = buf + OFF_V;
    float* attb = buf + OFF_ATT;
    float* qib  = buf + OFF_QI;
    float* kib  = buf + OFF_KI;
    float* isb  = buf + OFF_IS;
    float* yb   = buf + OFF_Y;
    float* hidb = buf + OFF_HID;

    // embedding
    embed_kernel<<<(NT * D + 255) / 256, 256>>>(input_ids, tok_emb, pos_emb, h);

    for (int l = 0; l < LAYERS; l++) {
        const float* iqw = ind_qw + (long)l * D * IHD;
        const float* iqb_ = ind_qb + (long)l * IHD;
        const float* ikw = ind_kw + (long)l * D * IHD;
        const float* ikb_ = ind_kb + (long)l * IHD;
        const float* ihw = ind_hw + (long)l * IH;

        // indexer projections (from raw h)
        sgemm_kernel<<<dim3(IHD / 64, NT / 64), 256>>>(h, iqw, iqb_, nullptr, qib, NT, IHD, D, nullptr, nullptr, 0);
        sgemm_kernel<<<dim3(IHD / 64, NT / 64), 256>>>(h, ikw, ikb_, nullptr, kib, NT, IHD, D, nullptr, nullptr, 0);
        // scores + top-k selection
        idx_score_kernel<<<NT, 256>>>(qib, kib, ihw, isb);
        topk_kernel<<<NT, 1024>>>(isb, selmask);

        // attention pre-LN
        ln_kernel<<<NT, 256>>>(h, an_g + (long)l * D, an_b + (long)l * D, hn);
        sgemm_kernel<<<dim3(D / 64, NT / 64), 256>>>(hn, q_w + (long)l * D * D, q_b + (long)l * D, nullptr, qb, NT, D, D, nullptr, nullptr, 0);
        sgemm_kernel<<<dim3(D / 64, NT / 64), 256>>>(hn, k_w + (long)l * D * D, k_b + (long)l * D, nullptr, kb, NT, D, D, nullptr, nullptr, 0);
        sgemm_kernel<<<dim3(D / 64, NT / 64), 256>>>(hn, v_w + (long)l * D * D, v_b + (long)l * D, nullptr, vb, NT, D, D, nullptr, nullptr, 0);
        attn_kernel<<<B * H * S, 256>>>(qb, kb, vb, selmask, attb);
        // output proj + residual
        sgemm_kernel<<<dim3(D / 64, NT / 64), 256>>>(attb, o_w + (long)l * D * D, o_b + (long)l * D, h, h, NT, D, D, nullptr, nullptr, 0);

        // MoE
        ln_kernel<<<NT, 256>>>(h, mn_g + (long)l * D, mn_b + (long)l * D, hn);
        zero_counts_kernel<<<1, 32>>>(ecount);
        router_kernel<<<NT, 256>>>(hn, router_w + (long)l * D * NE, router_b + (long)l * NE,
                                   tope, gate, slot, elist, ecount);
        for (int e = 0; e < NE; e++) {
            const float* w1 = e_w1 + ((long)l * NE + e) * (long)D * FF;
            const float* b1 = e_b1 + ((long)l * NE + e) * FF;
            sgemm_kernel<<<dim3(FF / 64, NT / 64), 256>>>(hn, w1, b1, nullptr,
                hidb + (long)e * NT * FF, NT, FF, D, elist + e * NT, ecount + e, 1);
        }
        for (int e = 0; e < NE; e++) {
            const float* w2 = e_w2 + ((long)l * NE + e) * (long)FF * D;
            const float* b2 = e_b2 + ((long)l * NE + e) * D;
            sgemm_kernel<<<dim3(D / 64, NT / 64), 256>>>(hidb + (long)e * NT * FF, w2, b2, nullptr,
                yb + (long)e * NT * D, NT, D, FF, nullptr, ecount + e, 0);
        }
        moe_gather_kernel<<<(NT * D + 255) / 256, 256>>>(yb, tope, gate, slot, h);
    }

    // final LN + logits
    ln_kernel<<<NT, 256>>>(h, ln_g, ln_b, hn);
    sgemm_kernel<<<dim3(V / 64, NT / 64), 256>>>(hn, out_w, out_b, nullptr, out, NT, V, D, nullptr, nullptr, 0);
}